// round 7
// baseline (speedup 1.0000x reference)
#include <cuda_runtime.h>
#include <math.h>
#include <stdint.h>

#define N_NODES 346
#define L_SEQ   50
#define D_EMB   300
#define H_HID   300
#define G4      1200   // 4*H

// ---------------------------------------------------------------------------
// Scratch pool (static device allocation — no cudaMalloc anywhere)
// ---------------------------------------------------------------------------
constexpr size_t A256(size_t x) { return (x + 255) & ~(size_t)255; }

constexpr size_t SZ_X   = (size_t)L_SEQ * N_NODES * D_EMB;
constexpr size_t SZ_P   = (size_t)L_SEQ * N_NODES * G4;
constexpr size_t SZ_O0  = (size_t)L_SEQ * N_NODES * 600;
constexpr size_t SZ_NG4 = (size_t)N_NODES * G4;
constexpr size_t SZ_NH  = (size_t)N_NODES * H_HID;

constexpr size_t OFF_X    = 0;
constexpr size_t OFF_P0F  = A256(OFF_X   + SZ_X);
constexpr size_t OFF_P0B  = A256(OFF_P0F + SZ_P);
constexpr size_t OFF_O0   = A256(OFF_P0B + SZ_P);
constexpr size_t OFF_HSA  = A256(OFF_O0  + SZ_O0);
constexpr size_t OFF_HSB  = A256(OFF_HSA + SZ_NG4);
constexpr size_t OFF_C4   = A256(OFF_HSB + SZ_NG4);
constexpr size_t OFF_CAT  = A256(OFF_C4  + 4 * SZ_NH);
constexpr size_t OFF_WH   = A256(OFF_CAT + (size_t)N_NODES * 2400);
constexpr size_t OFF_ATT  = A256(OFF_WH  + SZ_NG4);
constexpr size_t OFF_HS1  = A256(OFF_ATT + (size_t)N_NODES * N_NODES);
constexpr size_t OFF_HS2  = A256(OFF_HS1 + SZ_NG4);
constexpr size_t OFF_Z    = A256(OFF_HS2 + SZ_NG4);
constexpr size_t OFF_HC3  = A256(OFF_Z   + (size_t)N_NODES * 4800);
constexpr size_t OFF_WHHR  = A256(OFF_HC3  + (size_t)N_NODES * 9600);
constexpr size_t OFF_WIHR0 = A256(OFF_WHHR + 4 * (size_t)G4 * H_HID);
constexpr size_t OFF_WIHR1 = A256(OFF_WIHR0 + 2 * (size_t)G4 * 300);
constexpr size_t OFF_BR    = A256(OFF_WIHR1 + 2 * (size_t)G4 * 600);
constexpr size_t OFF_U    = A256(OFF_BR  + 4 * (size_t)G4);
constexpr size_t OFF_V    = A256(OFF_U   + 512);
constexpr size_t OFF_S    = A256(OFF_V   + 32);
constexpr size_t OFF_E1   = A256(OFF_S   + 1280);
constexpr size_t OFF_E2   = A256(OFF_E1  + 512);
constexpr size_t OFF_BATT = A256(OFF_E2  + 512);
constexpr size_t OFF_EA   = A256(OFF_BATT + 512);
constexpr size_t POOL_SZ  = A256(OFF_EA + 2560);

__device__ float g_pool[POOL_SZ];

__device__ __forceinline__ float sigm_(float x) { return 1.0f / (1.0f + expf(-x)); }

// ---------------------------------------------------------------------------
// Packed f32x2 helpers (Blackwell FFMA2: 2 fp32 FMAs per issue, IEEE-exact)
// ---------------------------------------------------------------------------
__device__ __forceinline__ uint64_t pack2f(float x) {
    uint64_t r;
    uint32_t u = __float_as_uint(x);
    asm("mov.b64 %0, {%1, %1};" : "=l"(r) : "r"(u));
    return r;
}
__device__ __forceinline__ void fma2(uint64_t& c, uint64_t a, uint64_t b) {
    asm("fma.rn.f32x2 %0, %1, %2, %0;" : "+l"(c) : "l"(a), "l"(b));
}
__device__ __forceinline__ float2 unpack2(uint64_t v) {
    uint32_t lo, hi;
    asm("mov.b64 {%0, %1}, %2;" : "=r"(lo), "=r"(hi) : "l"(v));
    return make_float2(__uint_as_float(lo), __uint_as_float(hi));
}

// ---------------------------------------------------------------------------
// 64x64x16 GEMM accumulator core, f32x2 accumulators (4x2 pairs per thread)
//   TB=1 : C[m][n] = sum_k A[m*lda+k] * B[n*ldb+k]
//   TB=0 : C[m][n] = sum_k A[m*lda+k] * B[k*ldb+n]
// ---------------------------------------------------------------------------
#define BM 64
#define BN 64
#define BK 16
#define SPAD 68

template<int TB>
__device__ __forceinline__ void gemm_acc64(
    int M, int N, int K,
    const float* __restrict__ A, int lda,
    const float* __restrict__ B, int ldb,
    float* As, float* Bs, uint64_t acc2[4][2],
    int m0, int n0, int tid, int tx, int ty)
{
#pragma unroll
    for (int i = 0; i < 4; i++) { acc2[i][0] = 0ull; acc2[i][1] = 0ull; }

    for (int k0 = 0; k0 < K; k0 += BK) {
#pragma unroll
        for (int i = 0; i < 4; i++) {
            int idx = tid + i * 256;
            int m = idx >> 4, k = idx & 15;
            int gm = m0 + m, gk = k0 + k;
            As[k * SPAD + m] = (gm < M && gk < K) ? __ldg(&A[(size_t)gm * lda + gk]) : 0.0f;
        }
        if (TB) {
#pragma unroll
            for (int i = 0; i < 4; i++) {
                int idx = tid + i * 256;
                int j = idx >> 4, k = idx & 15;
                int gj = n0 + j, gk = k0 + k;
                Bs[k * SPAD + j] = (gj < N && gk < K) ? __ldg(&B[(size_t)gj * ldb + gk]) : 0.0f;
            }
        } else {
#pragma unroll
            for (int i = 0; i < 4; i++) {
                int idx = tid + i * 256;
                int j = idx & 63, k = idx >> 6;
                int gj = n0 + j, gk = k0 + k;
                Bs[k * SPAD + j] = (gj < N && gk < K) ? __ldg(&B[(size_t)gk * ldb + gj]) : 0.0f;
            }
        }
        __syncthreads();
#pragma unroll
        for (int kk = 0; kk < BK; kk++) {
            float4 av = *reinterpret_cast<const float4*>(&As[kk * SPAD + ty * 4]);
            ulonglong2 bv = *reinterpret_cast<const ulonglong2*>(&Bs[kk * SPAD + tx * 4]);
            uint64_t ap[4] = {pack2f(av.x), pack2f(av.y), pack2f(av.z), pack2f(av.w)};
#pragma unroll
            for (int i = 0; i < 4; i++) {
                fma2(acc2[i][0], ap[i], bv.x);
                fma2(acc2[i][1], ap[i], bv.y);
            }
        }
        __syncthreads();
    }
}

// Generic 64x64 GEMM with epilogue: EPI 0 none, 1 tanh, 2 elu
template<int TB, int EPI>
__global__ void __launch_bounds__(256) gemm_kernel(
    int M, int N, int K,
    const float* __restrict__ A, int lda,
    const float* __restrict__ B, int ldb,
    const float* __restrict__ Dm, int ldd,
    float* __restrict__ C, int ldc)
{
    __shared__ float As[BK * SPAD], Bs[BK * SPAD];
    const int m0 = blockIdx.y * BM, n0 = blockIdx.x * BN;
    const int tid = threadIdx.x, tx = tid & 15, ty = tid >> 4;
    uint64_t acc2[4][2];
    gemm_acc64<TB>(M, N, K, A, lda, B, ldb, As, Bs, acc2, m0, n0, tid, tx, ty);

#pragma unroll
    for (int i = 0; i < 4; i++) {
        int gm = m0 + ty * 4 + i;
        if (gm >= M) continue;
        float2 v0 = unpack2(acc2[i][0]);
        float2 v1 = unpack2(acc2[i][1]);
        float vals[4] = {v0.x, v0.y, v1.x, v1.y};
#pragma unroll
        for (int j = 0; j < 4; j++) {
            int gn = n0 + tx * 4 + j;
            if (gn >= N) continue;
            float v = vals[j];
            if (Dm) v += (ldd == 0) ? Dm[gn] : Dm[(size_t)gm * ldd + gn];
            if (EPI == 1) v = tanhf(v);
            if (EPI == 2) v = (v > 0.0f) ? v : expm1f(v);
            C[(size_t)gm * ldc + gn] = v;
        }
    }
}

// ---------------------------------------------------------------------------
// 128x128x8 GEMM, 8x8 per thread, f32x2 accumulators (8x4 pairs)
// ---------------------------------------------------------------------------
#define XBM 128
#define XBN 128
#define XBK 8
#define XPAD 132

template<int TB, int EPI>
__global__ void __launch_bounds__(256) gemm128_kernel(
    int M, int N, int K,
    const float* __restrict__ A, int lda,
    const float* __restrict__ B, int ldb,
    const float* __restrict__ Dm, int ldd,
    float* __restrict__ C, int ldc)
{
    __shared__ float As[XBK * XPAD], Bs[XBK * XPAD];
    const int m0 = blockIdx.y * XBM, n0 = blockIdx.x * XBN;
    const int tid = threadIdx.x, tx = tid & 15, ty = tid >> 4;

    uint64_t acc2[8][4];
#pragma unroll
    for (int i = 0; i < 8; i++)
#pragma unroll
        for (int j = 0; j < 4; j++) acc2[i][j] = 0ull;

    for (int k0 = 0; k0 < K; k0 += XBK) {
#pragma unroll
        for (int l = 0; l < 4; l++) {
            int idx = tid + l * 256;
            int m = idx >> 3, k = idx & 7;
            int gm = m0 + m, gk = k0 + k;
            As[k * XPAD + m] = (gm < M && gk < K) ? __ldg(&A[(size_t)gm * lda + gk]) : 0.0f;
        }
        if (TB) {
#pragma unroll
            for (int l = 0; l < 4; l++) {
                int idx = tid + l * 256;
                int j = idx >> 3, k = idx & 7;
                int gj = n0 + j, gk = k0 + k;
                Bs[k * XPAD + j] = (gj < N && gk < K) ? __ldg(&B[(size_t)gj * ldb + gk]) : 0.0f;
            }
        } else {
#pragma unroll
            for (int l = 0; l < 4; l++) {
                int idx = tid + l * 256;
                int k = idx >> 7, j = idx & 127;
                int gj = n0 + j, gk = k0 + k;
                Bs[k * XPAD + j] = (gj < N && gk < K) ? __ldg(&B[(size_t)gk * ldb + gj]) : 0.0f;
            }
        }
        __syncthreads();
#pragma unroll
        for (int kk = 0; kk < XBK; kk++) {
            float4 a0 = *reinterpret_cast<const float4*>(&As[kk * XPAD + ty * 8]);
            float4 a1 = *reinterpret_cast<const float4*>(&As[kk * XPAD + ty * 8 + 4]);
            ulonglong2 b0 = *reinterpret_cast<const ulonglong2*>(&Bs[kk * XPAD + tx * 8]);
            ulonglong2 b1 = *reinterpret_cast<const ulonglong2*>(&Bs[kk * XPAD + tx * 8 + 4]);
            uint64_t ap[8] = {pack2f(a0.x), pack2f(a0.y), pack2f(a0.z), pack2f(a0.w),
                              pack2f(a1.x), pack2f(a1.y), pack2f(a1.z), pack2f(a1.w)};
            uint64_t bp[4] = {b0.x, b0.y, b1.x, b1.y};
#pragma unroll
            for (int i = 0; i < 8; i++)
#pragma unroll
                for (int j = 0; j < 4; j++)
                    fma2(acc2[i][j], ap[i], bp[j]);
        }
        __syncthreads();
    }

#pragma unroll
    for (int i = 0; i < 8; i++) {
        int gm = m0 + ty * 8 + i;
        if (gm >= M) continue;
#pragma unroll
        for (int jp = 0; jp < 4; jp++) {
            float2 v2 = unpack2(acc2[i][jp]);
            float vv[2] = {v2.x, v2.y};
#pragma unroll
            for (int l = 0; l < 2; l++) {
                int gn = n0 + tx * 8 + jp * 2 + l;
                if (gn >= N) continue;
                float v = vv[l];
                if (Dm) v += (ldd == 0) ? Dm[gn] : Dm[(size_t)gm * ldd + gn];
                if (EPI == 1) v = tanhf(v);
                if (EPI == 2) v = (v > 0.0f) ? v : expm1f(v);
                C[(size_t)gm * ldc + gn] = v;
            }
        }
    }
}

// ---------------------------------------------------------------------------
// Fused LSTM step (gate-interleaved weights, cell update in epilogue)
// ---------------------------------------------------------------------------
__global__ void __launch_bounds__(256) lstm_fused_kernel(
    const float* __restrict__ hs_in, float* __restrict__ hs_out,
    int hcol_f, int hcol_b,
    const float* __restrict__ Whh_rf, const float* __restrict__ Whh_rb,
    const float* __restrict__ Pf, const float* __restrict__ Pb,
    float* __restrict__ cbuf,            // [2][N][H]
    float* __restrict__ outbuf, int t)   // o0 or null
{
    __shared__ float As[BK * SPAD], Bs[BK * SPAD];
    const int z = blockIdx.z;
    const int hcol = z ? hcol_b : hcol_f;
    const float* A = hs_in + hcol;
    const float* Bw = z ? Whh_rb : Whh_rf;
    const float* P  = z ? Pb : Pf;

    const int m0 = blockIdx.y * BM, n0 = blockIdx.x * BN;
    const int tid = threadIdx.x, tx = tid & 15, ty = tid >> 4;
    uint64_t acc2[4][2];
    gemm_acc64<1>(N_NODES, G4, H_HID, A, G4, Bw, H_HID, As, Bs, acc2, m0, n0, tid, tx, ty);

    const int r0 = n0 + tx * 4;
    if (r0 + 3 >= G4) return;
    const int j = r0 >> 2;
    float* c = cbuf + (size_t)z * N_NODES * H_HID;

#pragma unroll
    for (int i = 0; i < 4; i++) {
        int gm = m0 + ty * 4 + i;
        if (gm >= N_NODES) continue;
        float4 p = *reinterpret_cast<const float4*>(P + (size_t)gm * G4 + r0);
        float2 v0 = unpack2(acc2[i][0]);   // (i, f)
        float2 v1 = unpack2(acc2[i][1]);   // (g, o)
        float gi = v0.x + p.x;
        float gf = v0.y + p.y;
        float gg = v1.x + p.z;
        float go = v1.y + p.w;
        float cp = c[(size_t)gm * H_HID + j];
        float cn = sigm_(gf) * cp + sigm_(gi) * tanhf(gg);
        float h  = sigm_(go) * tanhf(cn);
        c[(size_t)gm * H_HID + j] = cn;
        hs_out[(size_t)gm * G4 + hcol + j] = h;
        if (outbuf) {
            int tt = z ? (L_SEQ - 1 - t) : t;
            outbuf[(size_t)tt * N_NODES * 600 + (size_t)gm * 600 + z * H_HID + j] = h;
        }
    }
}

// Reorder LSTM weight rows: out[j*4+g][k] = in[g*H + j][k]
__global__ void reorder_rows_kernel(const float* __restrict__ in,
                                    float* __restrict__ out, int K)
{
    size_t idx = (size_t)blockIdx.x * blockDim.x + threadIdx.x;
    if (idx >= (size_t)G4 * K) return;
    int r = (int)(idx / K), k = (int)(idx % K);
    int j = r >> 2, g = r & 3;
    out[(size_t)r * K + k] = in[(size_t)(g * H_HID + j) * K + k];
}

__global__ void memzero_kernel(float* p, int n)
{
    int i = blockIdx.x * blockDim.x + threadIdx.x;
    if (i < n) p[i] = 0.0f;
}

__global__ void embed_kernel(const int* __restrict__ tok,
                             const float* __restrict__ emb,
                             float* __restrict__ x)
{
    size_t idx = (size_t)blockIdx.x * blockDim.x + threadIdx.x;
    const size_t total = (size_t)L_SEQ * N_NODES * D_EMB;
    if (idx >= total) return;
    int d = (int)(idx % D_EMB);
    size_t r = idx / D_EMB;
    int n = (int)(r % N_NODES);
    int t = (int)(r / N_NODES);
    int tv = tok[n * L_SEQ + t];
    x[idx] = emb[(size_t)tv * D_EMB + d];
}

// out[row] = epi( dot(A[row,:K], w) )
template<int EPI>
__global__ void rows_dot_kernel(const float* __restrict__ A, int lda,
                                const float* __restrict__ w, int K,
                                float* __restrict__ out)
{
    __shared__ float red[8];
    const float* a = A + (size_t)blockIdx.x * lda;
    float s = 0.0f;
    for (int k = threadIdx.x; k < K; k += blockDim.x) s += a[k] * w[k];
#pragma unroll
    for (int o = 16; o > 0; o >>= 1) s += __shfl_down_sync(0xffffffffu, s, o);
    if ((threadIdx.x & 31) == 0) red[threadIdx.x >> 5] = s;
    __syncthreads();
    if (threadIdx.x == 0) {
        float t = 0.0f;
        int nw = blockDim.x >> 5;
        for (int i = 0; i < nw; i++) t += red[i];
        if (EPI == 1) t = tanhf(t);
        out[blockIdx.x] = t;
    }
}

// out[j] = scale * sum_n (w ? w[n] : 1) * A[n*lda + j]
__global__ void colsum_kernel(const float* __restrict__ A, int lda, int rows,
                              const float* __restrict__ w, float scale,
                              float* __restrict__ out, int ncols)
{
    int j = blockIdx.x * blockDim.x + threadIdx.x;
    if (j >= ncols) return;
    float s = 0.0f;
#pragma unroll 4
    for (int n = 0; n < rows; n++) {
        float v = A[(size_t)n * lda + j];
        s += w ? w[n] * v : v;
    }
    out[j] = s * scale;
}

// cat[n] = [ h[n] , gate(h)[n] ]
__global__ void gate_cat_kernel(const float* __restrict__ h,
                                const float* __restrict__ u,
                                const float* __restrict__ vsc,
                                const float* __restrict__ s,
                                float* __restrict__ cat)
{
    int idx = blockIdx.x * blockDim.x + threadIdx.x;
    if (idx >= N_NODES * G4) return;
    int n = idx / G4, j = idx % G4;
    float hv = h[(size_t)n * G4 + j];
    float h0 = h[j];
    float val;
    if (n == 0) {
        val = h0;
    } else {
        float g = sigm_(u[n] + vsc[0]);
        val = g * s[j] + (1.0f - g) * ((float)(N_NODES - 1) * h0);
    }
    cat[(size_t)n * 2400 + j] = hv;
    cat[(size_t)n * 2400 + 1200 + j] = val;
}

__global__ void att_softmax_kernel(const float* __restrict__ e1,
                                   const float* __restrict__ e2,
                                   const int* __restrict__ adj,
                                   float* __restrict__ att)
{
    __shared__ float warpred[4];
    __shared__ float s_max, s_sum;
    int i = blockIdx.x;
    float ei = e1[i];

    float mx = -3.4e38f;
    for (int j = threadIdx.x; j < N_NODES; j += blockDim.x) {
        float v = ei + e2[j];
        v = (v > 0.0f) ? v : 0.01f * v;
        if (adj[(size_t)i * N_NODES + j] <= 0) v = -9.0e15f;
        mx = fmaxf(mx, v);
    }
#pragma unroll
    for (int o = 16; o > 0; o >>= 1) mx = fmaxf(mx, __shfl_down_sync(0xffffffffu, mx, o));
    if ((threadIdx.x & 31) == 0) warpred[threadIdx.x >> 5] = mx;
    __syncthreads();
    if (threadIdx.x == 0) {
        float m2 = warpred[0];
        int nw = blockDim.x >> 5;
        for (int k = 1; k < nw; k++) m2 = fmaxf(m2, warpred[k]);
        s_max = m2;
    }
    __syncthreads();
    float smax = s_max;

    float sum = 0.0f;
    for (int j = threadIdx.x; j < N_NODES; j += blockDim.x) {
        float v = ei + e2[j];
        v = (v > 0.0f) ? v : 0.01f * v;
        if (adj[(size_t)i * N_NODES + j] <= 0) v = -9.0e15f;
        sum += expf(v - smax);
    }
#pragma unroll
    for (int o = 16; o > 0; o >>= 1) sum += __shfl_down_sync(0xffffffffu, sum, o);
    if ((threadIdx.x & 31) == 0) warpred[threadIdx.x >> 5] = sum;
    __syncthreads();
    if (threadIdx.x == 0) {
        float t = 0.0f;
        int nw = blockDim.x >> 5;
        for (int k = 0; k < nw; k++) t += warpred[k];
        s_sum = t;
    }
    __syncthreads();
    float inv = 1.0f / s_sum;

    for (int j = threadIdx.x; j < N_NODES; j += blockDim.x) {
        float v = ei + e2[j];
        v = (v > 0.0f) ? v : 0.01f * v;
        if (adj[(size_t)i * N_NODES + j] <= 0) v = -9.0e15f;
        att[(size_t)i * N_NODES + j] = expf(v - smax) * inv;
    }
}

// Z[n] = [hc, hs2[n], hc*hs2[n], hc - hs2[n]],  hc = hs2[0]
__global__ void zassemble_kernel(const float* __restrict__ h2, float* __restrict__ Z)
{
    int idx = blockIdx.x * blockDim.x + threadIdx.x;
    if (idx >= N_NODES * G4) return;
    int n = idx / G4, j = idx % G4;
    float a = h2[j];
    float b = h2[(size_t)n * G4 + j];
    size_t base = (size_t)n * 4800;
    Z[base + j]        = a;
    Z[base + 1200 + j] = b;
    Z[base + 2400 + j] = a * b;
    Z[base + 3600 + j] = a - b;
}

__global__ void final_kernel(const float* __restrict__ ea,
                             const float* __restrict__ Wlin,
                             const float* __restrict__ blin,
                             float* __restrict__ out)
{
    __shared__ float r0[8], r1[8];
    float s0 = 0.0f, s1 = 0.0f;
    for (int j = threadIdx.x; j < 2400; j += blockDim.x) {
        float e = ea[j];
        s0 += e * Wlin[j];
        s1 += e * Wlin[2400 + j];
    }
#pragma unroll
    for (int o = 16; o > 0; o >>= 1) {
        s0 += __shfl_down_sync(0xffffffffu, s0, o);
        s1 += __shfl_down_sync(0xffffffffu, s1, o);
    }
    if ((threadIdx.x & 31) == 0) { r0[threadIdx.x >> 5] = s0; r1[threadIdx.x >> 5] = s1; }
    __syncthreads();
    if (threadIdx.x == 0) {
        float l0 = 0.0f, l1 = 0.0f;
        int nw = blockDim.x >> 5;
        for (int i = 0; i < nw; i++) { l0 += r0[i]; l1 += r1[i]; }
        l0 += blin[0]; l1 += blin[1];
        float m = fmaxf(l0, l1);
        float e0 = expf(l0 - m), e1v = expf(l1 - m);
        float inv = 1.0f / (e0 + e1v);
        out[0] = e0 * inv;
        out[1] = e1v * inv;
    }
}

// ---------------------------------------------------------------------------
// Host orchestration
// ---------------------------------------------------------------------------
static inline dim3 grid64(int M, int N)  { return dim3((N + BN - 1) / BN, (M + BM - 1) / BM); }
static inline dim3 grid128(int M, int N) { return dim3((N + XBN - 1) / XBN, (M + XBM - 1) / XBM); }

static void run_gate_gat(const float* h_in, float* h_out,
                         const float* gate_W, const float* gate_U,
                         const float* W_gat, const float* a_gat,
                         const int* adj, float* pool)
{
    float* U   = pool + OFF_U;
    float* Vb  = pool + OFF_V;
    float* S   = pool + OFF_S;
    float* CAT = pool + OFF_CAT;
    float* WHp = pool + OFF_WH;
    float* E1  = pool + OFF_E1;
    float* E2  = pool + OFF_E2;
    float* ATT = pool + OFF_ATT;

    rows_dot_kernel<0><<<N_NODES, 256>>>(h_in, G4, gate_W, G4, U);
    rows_dot_kernel<0><<<1, 256>>>(h_in, G4, gate_U, G4, Vb);
    colsum_kernel<<<(G4 + 255) / 256, 256>>>(h_in + G4, G4, N_NODES - 1, nullptr, 1.0f, S, G4);
    gate_cat_kernel<<<(N_NODES * G4 + 255) / 256, 256>>>(h_in, U, Vb, S, CAT);

    gemm_kernel<0, 0><<<grid64(N_NODES, G4), 256>>>(
        N_NODES, G4, 2400, CAT, 2400, W_gat, G4, nullptr, 0, WHp, G4);
    rows_dot_kernel<0><<<N_NODES, 256>>>(WHp, G4, a_gat, G4, E1);
    rows_dot_kernel<0><<<N_NODES, 256>>>(WHp, G4, a_gat + G4, G4, E2);
    att_softmax_kernel<<<N_NODES, 128>>>(E1, E2, adj, ATT);
    gemm_kernel<0, 2><<<grid64(N_NODES, G4), 256>>>(
        N_NODES, G4, N_NODES, ATT, N_NODES, WHp, G4, nullptr, 0, h_out, G4);
}

extern "C" void kernel_launch(void* const* d_in, const int* in_sizes, int n_in,
                              void* d_out, int out_size)
{
    (void)in_sizes; (void)n_in; (void)out_size;

    float* pool = nullptr;
    cudaGetSymbolAddress((void**)&pool, g_pool);

    const int*   tokens  = (const int*)d_in[0];
    const int*   adj     = (const int*)d_in[1];
    const float* emb     = (const float*)d_in[2];
    const float* Wih_l0f = (const float*)d_in[3];
    const float* Whh_l0f = (const float*)d_in[4];
    const float* b_l0f   = (const float*)d_in[5];
    const float* Wih_l0b = (const float*)d_in[6];
    const float* Whh_l0b = (const float*)d_in[7];
    const float* b_l0b   = (const float*)d_in[8];
    const float* Wih_l1f = (const float*)d_in[9];
    const float* Whh_l1f = (const float*)d_in[10];
    const float* b_l1f   = (const float*)d_in[11];
    const float* Wih_l1b = (const float*)d_in[12];
    const float* Whh_l1b = (const float*)d_in[13];
    const float* b_l1b   = (const float*)d_in[14];
    const float* W_gat   = (const float*)d_in[15];
    const float* a_gat   = (const float*)d_in[16];
    const float* gate_W  = (const float*)d_in[17];
    const float* gate_U  = (const float*)d_in[18];
    const float* FC1     = (const float*)d_in[19];
    const float* FC2     = (const float*)d_in[20];
    const float* Wlin    = (const float*)d_in[21];
    const float* blin    = (const float*)d_in[22];
    float* out = (float*)d_out;

    float* X    = pool + OFF_X;
    float* PF   = pool + OFF_P0F;
    float* PB   = pool + OFF_P0B;
    float* O0   = pool + OFF_O0;
    float* HSA  = pool + OFF_HSA;
    float* HSB  = pool + OFF_HSB;
    float* C4   = pool + OFF_C4;
    float* HS1  = pool + OFF_HS1;
    float* HS2  = pool + OFF_HS2;
    float* Z    = pool + OFF_Z;
    float* HC3  = pool + OFF_HC3;
    float* WHHR  = pool + OFF_WHHR;   // 4 x [1200][300]: l0f,l0b,l1f,l1b
    float* WIHR0 = pool + OFF_WIHR0;  // 2 x [1200][300]
    float* WIHR1 = pool + OFF_WIHR1;  // 2 x [1200][600]
    float* BR    = pool + OFF_BR;     // 4 x [1200]
    float* BATT = pool + OFF_BATT;
    float* EA   = pool + OFF_EA;

    const int LN = L_SEQ * N_NODES;   // 17300
    const size_t W3 = (size_t)G4 * 300, W6 = (size_t)G4 * 600;

    const int thr = 256;
    const int g3 = (int)((W3 + thr - 1) / thr), g6 = (int)((W6 + thr - 1) / thr);
    const int g1 = (G4 + thr - 1) / thr;

    // Launches 0-3: only what proj-l0 needs (so ncu slot #5 = proj-l0 GEMM)
    reorder_rows_kernel<<<g3, thr>>>(Wih_l0f, WIHR0 + 0 * W3, 300);
    reorder_rows_kernel<<<g3, thr>>>(Wih_l0b, WIHR0 + 1 * W3, 300);
    reorder_rows_kernel<<<g1, thr>>>(b_l0f, BR + 0 * G4, 1);
    reorder_rows_kernel<<<g1, thr>>>(b_l0b, BR + 1 * G4, 1);
    // Launch 4: embedding
    embed_kernel<<<(int)((SZ_X + 255) / 256), 256>>>(tokens, emb, X);
    // Launch 5 (ncu-profiled): layer-0 forward projection
    gemm128_kernel<1, 0><<<grid128(LN, G4), 256>>>(
        LN, G4, D_EMB, X, D_EMB, WIHR0 + 0 * W3, 300, BR + 0 * G4, 0, PF, G4);
    gemm128_kernel<1, 0><<<grid128(LN, G4), 256>>>(
        LN, G4, D_EMB, X, D_EMB, WIHR0 + 1 * W3, 300, BR + 1 * G4, 0, PB, G4);

    // Remaining weight prep + state init
    reorder_rows_kernel<<<g3, thr>>>(Whh_l0f, WHHR + 0 * W3, 300);
    reorder_rows_kernel<<<g3, thr>>>(Whh_l0b, WHHR + 1 * W3, 300);
    reorder_rows_kernel<<<g3, thr>>>(Whh_l1f, WHHR + 2 * W3, 300);
    reorder_rows_kernel<<<g3, thr>>>(Whh_l1b, WHHR + 3 * W3, 300);
    reorder_rows_kernel<<<g6, thr>>>(Wih_l1f, WIHR1 + 0 * W6, 600);
    reorder_rows_kernel<<<g6, thr>>>(Wih_l1b, WIHR1 + 1 * W6, 600);
    reorder_rows_kernel<<<g1, thr>>>(b_l1f, BR + 2 * G4, 1);
    reorder_rows_kernel<<<g1, thr>>>(b_l1b, BR + 3 * G4, 1);
    memzero_kernel<<<((int)SZ_NG4 + 255) / 256, 256>>>(HSA, (int)SZ_NG4);
    memzero_kernel<<<(4 * (int)SZ_NH + 255) / 256, 256>>>(C4, 4 * (int)SZ_NH);

    // ---- layer-0 scan (fused GEMM+cell, h double-buffered) ----
    {
        dim3 grid = grid64(N_NODES, G4); grid.z = 2;
        const float* hin = HSA; float* hout = HSB;
        for (int t = 0; t < L_SEQ; t++) {
            lstm_fused_kernel<<<grid, 256>>>(
                hin, hout, 0, 300,
                WHHR + 0 * W3, WHHR + 1 * W3,
                PF + (size_t)t * N_NODES * G4,
                PB + (size_t)(L_SEQ - 1 - t) * N_NODES * G4,
                C4, O0, t);
            const float* tmp = hin; hin = hout; hout = (float*)tmp;
        }
    }

    // ---- layer-1 input projections ----
    gemm128_kernel<1, 0><<<grid128(LN, G4), 256>>>(
        LN, G4, 600, O0, 600, WIHR1 + 0 * W6, 600, BR + 2 * G4, 0, PF, G4);
    gemm128_kernel<1, 0><<<grid128(LN, G4), 256>>>(
        LN, G4, 600, O0, 600, WIHR1 + 1 * W6, 600, BR + 3 * G4, 0, PB, G4);

    // ---- layer-1 scan (cols 600/900, c slices 2,3) ----
    {
        dim3 grid = grid64(N_NODES, G4); grid.z = 2;
        const float* hin = HSA; float* hout = HSB;
        for (int t = 0; t < L_SEQ; t++) {
            lstm_fused_kernel<<<grid, 256>>>(
                hin, hout, 600, 900,
                WHHR + 2 * W3, WHHR + 3 * W3,
                PF + (size_t)t * N_NODES * G4,
                PB + (size_t)(L_SEQ - 1 - t) * N_NODES * G4,
                C4 + 2 * SZ_NH, nullptr, t);
            const float* tmp = hin; hin = hout; hout = (float*)tmp;
        }
    }
    // L_SEQ=50 (even): final h for both layers lands in HSA.

    // ---- two gate+GAT stages ----
    run_gate_gat(HSA, HS1, gate_W, gate_U, W_gat, a_gat, adj, pool);
    run_gate_gat(HS1, HS2, gate_W, gate_U, W_gat, a_gat, adj, pool);

    // ---- final head ----
    zassemble_kernel<<<(N_NODES * G4 + 255) / 256, 256>>>(HS2, Z);
    gemm128_kernel<0, 1><<<grid128(N_NODES, 9600), 256>>>(
        N_NODES, 9600, 4800, Z, 4800, FC1, 9600, nullptr, 0, HC3, 9600);
    rows_dot_kernel<1><<<N_NODES, 256>>>(HC3, 9600, FC2, 9600, BATT);
    colsum_kernel<<<(G4 + 255) / 256, 256>>>(HS2, G4, N_NODES, nullptr,
                                             1.0f / (float)N_NODES, EA, G4);
    colsum_kernel<<<(G4 + 255) / 256, 256>>>(HS2, G4, N_NODES, BATT, 1.0f, EA + G4, G4);
    final_kernel<<<1, 256>>>(EA, Wlin, blin, out);
}